// round 15
// baseline (speedup 1.0000x reference)
#include <cuda_runtime.h>
#include <cuda_fp16.h>
#include <math.h>

// Problem constants
#define NB 128
#define LL 24
#define NN 121
#define DD 121
#define NSTEP 6
#define BL 3072
#define OUT_TOTAL (NSTEP*BL*NN)
#define STEP_SLAB (BL*NN)

// K1 config
#define K1_BLOCKS 32
#define K1_ROWS 96
#define GP_SLABS (2*K1_BLOCKS)
#define K1_SMEM (K1_ROWS*121*4)

// Resident pack bases in uint units
#define UB_L1 0
#define UB_L2 8192
#define UB_N1 16384
#define UB_N2 32768
#define UB_F1 40960
#define UPK_TOTAL 49152  // uints -> 196608 bytes

// smem byte offsets (k2)
#define SB_BIAS   196608   // float[896]
#define SB_RED    200192   // float[4096]
#define SB_CATH2  216576   // uint[256]
#define SB_L1H2   217600   // uint[128]
#define SB_NETH2  218112   // uint[128]
#define SB_XTH2   218624   // uint[128]
#define SB_XTF    219136   // float[128]
#define SB_DELTA  219648   // float[128]
#define SB_BC     220160   // float[128]
#define SB_OUTV   220672   // float[128]
#define SB_OUTVH2 221184   // uint[128]
#define SB_FEAT   221696   // float[128]
#define SB_COMPW  222208   // float[320]
#define SB_DUMMYF 223488   // float[128]
#define SMEM_BYTES 224000

// ---------------- device scratch ----------------
__device__ float d_gpart[GP_SLABS * 968];
__device__ float d_preds[NSTEP * DD];
__device__ __align__(16) unsigned int d_hpack[UPK_TOTAL];
__device__ __align__(16) unsigned int d_pk_fc23[8192];
__device__ __align__(16) unsigned int d_pk_fout[8192];

// ---------------- K0: fused k1 partial GEMM + weight packing (512 thr) ----------------
__global__ __launch_bounds__(512)
void k0(const float* __restrict__ x, const float* __restrict__ cw,
        const float* __restrict__ lw1, const float* __restrict__ lw2,
        const float* __restrict__ nw1, const float* __restrict__ nw2,
        const float* __restrict__ f1,  const float* __restrict__ f2,
        const float* __restrict__ f3,  const float* __restrict__ fo) {
    int b = blockIdx.x;
    int t = threadIdx.x;
    if (b < K1_BLOCKS) {
        extern __shared__ __align__(16) float xs[];
        __shared__ float cwsm[K1_ROWS * 8];
        int r0 = b * K1_ROWS;
        {
            const float4* src = (const float4*)(x + (long)r0 * 121);
            float4* dst = (float4*)xs;
#pragma unroll
            for (int i = 0; i < 6; ++i) {
                int idx = t + i * 512;
                if (idx < 2904) dst[idx] = src[idx];
            }
        }
        for (int j = t; j < K1_ROWS * 8; j += 512) cwsm[j] = cw[r0*8 + j];
        __syncthreads();
        int grp = -1, tt = 0;
        if (t < 121) { grp = 0; tt = t; }
        else if (t >= 128 && t < 249) { grp = 1; tt = t - 128; }
        if (grp >= 0) {
            int rbase = grp * 48;
            float acc[8];
#pragma unroll
            for (int j = 0; j < 8; ++j) acc[j] = 0.f;
#pragma unroll 4
            for (int r = 0; r < 48; ++r) {
                float xv = xs[(rbase + r)*121 + tt];
#pragma unroll
                for (int j = 0; j < 8; ++j)
                    acc[j] = fmaf(xv, cwsm[(rbase + r)*8 + j], acc[j]);
            }
#pragma unroll
            for (int j = 0; j < 8; ++j)
                d_gpart[(2*b + grp)*968 + j*121 + tt] = acc[j];
        }
        return;
    }
    // ---- pack (first 256 threads) ----
    if (t >= 256) return;
    int p = b - K1_BLOCKS;
    int q = t & 31, i = t >> 5;
    int dl = i >> 1;
    int ol = (2*i) & 3;
    int m, sg;
    if      (p < 32)  { m = 0; sg = p; }
    else if (p < 64)  { m = 1; sg = p - 32; }
    else if (p < 128) { m = 2; sg = p - 64; }
    else if (p < 160) { m = 3; sg = p - 128; }
    else if (p < 192) { m = 4; sg = p - 160; }
    else if (p < 224) { m = 5; sg = p - 192; }
    else              { m = 6; sg = p - 224; }
    int k = sg*4 + dl;
    int row, rvalid;
    if (m == 2) {
        row = (k < 128) ? k : (121 + (k - 128));
        rvalid = (k < 128) ? (k < 121) : ((k - 128) < 121);
    } else {
        row = k;
        rvalid = (k < ((m == 1 || m == 3) ? 128 : 121));
    }
    int o0 = q*4 + ol, o1 = o0 + 1;
    float v0 = 0.f, v1 = 0.f;
    if (rvalid) {
        switch (m) {
            case 0: v0 = lw1[row*128 + o0]; v1 = lw1[row*128 + o1]; break;
            case 1: v0 = (o0 < 121) ? lw2[row*121 + o0] : 0.f;
                    v1 = (o1 < 121) ? lw2[row*121 + o1] : 0.f; break;
            case 2: v0 = nw1[row*128 + o0]; v1 = nw1[row*128 + o1]; break;
            case 3: v0 = (o0 < 121) ? nw2[row*121 + o0] : 0.f;
                    v1 = (o1 < 121) ? nw2[row*121 + o1] : 0.f; break;
            case 4: v0 = (o0 < 121) ? f1[row*121 + o0] : 0.f;
                    v1 = (o1 < 121) ? f1[row*121 + o1] : 0.f; break;
            case 5: v0 = (o0 < 64) ? f2[row*64 + o0] : f3[row*64 + o0 - 64];
                    v1 = (o1 < 64) ? f2[row*64 + o1] : f3[row*64 + o1 - 64]; break;
            default:v0 = (o0 < 121) ? fo[row*121 + o0] : 0.f;
                    v1 = (o1 < 121) ? fo[row*121 + o1] : 0.f; break;
        }
    }
    __half2 hh = __floats2half2_rn(v0, v1);
    unsigned u = *(unsigned*)&hh;
    unsigned* dp; unsigned base;
    switch (m) {
        case 0: dp = d_hpack;   base = UB_L1; break;
        case 1: dp = d_hpack;   base = UB_L2; break;
        case 2: dp = d_hpack;   base = UB_N1; break;
        case 3: dp = d_hpack;   base = UB_N2; break;
        case 4: dp = d_hpack;   base = UB_F1; break;
        case 5: dp = d_pk_fc23; base = 0; break;
        default:dp = d_pk_fout; base = 0; break;
    }
    dp[base + (unsigned)sg*256u + (unsigned)(i >> 2)*128u + (unsigned)q*4u + (unsigned)(i & 3)] = u;
}

// ---------------- activations (fast-math) ----------------
#define ACT_NONE 0
#define ACT_RELU 1
#define ACT_TANH 2
#define ACT_SOFTPLUS 3

__device__ __forceinline__ float tanh_fast(float v) {
    float r;
    asm("tanh.approx.f32 %0, %1;" : "=f"(r) : "f"(v));
    return r;
}

template<int ACT>
__device__ __forceinline__ float actfn(float v) {
    if (ACT == ACT_RELU) return v > 0.f ? v : 0.f;
    if (ACT == ACT_TANH) return tanh_fast(v);
    if (ACT == ACT_SOFTPLUS) return v > 20.f ? v : __logf(1.f + __expf(v));
    return v;
}

// ---------------- cp.async ----------------
__device__ __forceinline__ void cp_async16(void* smem_dst, const void* gsrc) {
    unsigned saddr = (unsigned)__cvta_generic_to_shared(smem_dst);
    asm volatile("cp.async.cg.shared.global [%0], [%1], 16;" :: "r"(saddr), "l"(gsrc));
}

// ---------------- half2 chunk ----------------
__device__ __forceinline__ void h2_chunk(uint4 xh, uint4 w0, uint4 w1,
                                         float2& a01, float2& a23) {
    __half2 x0 = *(__half2*)&xh.x, x1 = *(__half2*)&xh.y;
    __half2 x2 = *(__half2*)&xh.z, x3 = *(__half2*)&xh.w;
    __half2 p01 = __hfma2(x0, *(__half2*)&w0.x, __hmul2(x1, *(__half2*)&w0.z));
    __half2 p23 = __hfma2(x0, *(__half2*)&w0.y, __hmul2(x1, *(__half2*)&w0.w));
    float2 f;
    f = __half22float2(p01); a01.x += f.x; a01.y += f.y;
    f = __half22float2(p23); a23.x += f.x; a23.y += f.y;
    p01 = __hfma2(x2, *(__half2*)&w1.x, __hmul2(x3, *(__half2*)&w1.z));
    p23 = __hfma2(x2, *(__half2*)&w1.y, __hmul2(x3, *(__half2*)&w1.w));
    f = __half22float2(p01); a01.x += f.x; a01.y += f.y;
    f = __half22float2(p23); a23.x += f.x; a23.y += f.y;
}

// ---------------- half2 matvec: 128 outputs, 512 threads = 16 slices ----------------
template<int ACT, int NSL>
__device__ __forceinline__ void mvh(const uint4* __restrict__ Wt,
                                    const float* __restrict__ biasp,
                                    const unsigned* __restrict__ inh2,
                                    float* __restrict__ outf,
                                    unsigned* __restrict__ outh2,
                                    float* __restrict__ red) {
    int tid = threadIdx.x;
    int q = tid & 31, s = tid >> 5;   // s: 0..15
    float2 a01 = make_float2(0.f, 0.f), a23 = make_float2(0.f, 0.f);
#pragma unroll
    for (int cc = 0; cc < NSL; ++cc) {
        int j = s + cc*16;
        uint4 xh = ((const uint4*)inh2)[j];
        const uint4* wb = Wt + j*64;
        h2_chunk(xh, wb[q], wb[q + 32], a01, a23);
    }
    ((float4*)red)[s*32 + q] = make_float4(a01.x, a01.y, a23.x, a23.y);
    __syncthreads();
    if (tid < 128) {
        float v0 = 0.f, v1 = 0.f, v2 = 0.f, v3 = 0.f;
#pragma unroll
        for (int ss = 0; ss < 4; ++ss) {
            v0 += red[(ss*4 + 0)*128 + tid];
            v1 += red[(ss*4 + 1)*128 + tid];
            v2 += red[(ss*4 + 2)*128 + tid];
            v3 += red[(ss*4 + 3)*128 + tid];
        }
        float v = ((v0 + v1) + (v2 + v3)) + biasp[tid];
        v = actfn<ACT>(v);
        outf[tid] = v;
        __half2 d2 = __half2half2(__float2half_rn(v));
        outh2[tid] = *(unsigned*)&d2;
    }
    __syncthreads();
}

// ---------------- fused F1+FC23: 256 outputs, 512 threads = 8 groups x 4 chunks ------
__device__ __forceinline__ void mv_fused(const uint4* __restrict__ Wf1,
                                         const uint4* __restrict__ Wfc,
                                         const float* __restrict__ biasp512,
                                         const unsigned* __restrict__ inh2,
                                         float* __restrict__ delta,
                                         float* __restrict__ bcv,
                                         float* __restrict__ red) {
    int tid = threadIdx.x;
    int qq = tid & 63, s = tid >> 6;      // s: 0..7
    int q = qq & 31;
    const uint4* base = (qq < 32) ? Wf1 : Wfc;
    float2 a01 = make_float2(0.f, 0.f), a23 = make_float2(0.f, 0.f);
#pragma unroll
    for (int cc = 0; cc < 4; ++cc) {
        int j = s + cc*8;
        uint4 xh = ((const uint4*)inh2)[j];
        const uint4* wb = base + j*64;
        h2_chunk(xh, wb[q], wb[q + 32], a01, a23);
    }
    ((float4*)red)[s*64 + qq] = make_float4(a01.x, a01.y, a23.x, a23.y);
    __syncthreads();
    if (tid < 256) {
        float v0 = 0.f, v1 = 0.f, v2 = 0.f, v3 = 0.f;
#pragma unroll
        for (int ss = 0; ss < 2; ++ss) {
            v0 += red[(ss*4 + 0)*256 + tid];
            v1 += red[(ss*4 + 1)*256 + tid];
            v2 += red[(ss*4 + 2)*256 + tid];
            v3 += red[(ss*4 + 3)*256 + tid];
        }
        float v = ((v0 + v1) + (v2 + v3)) + biasp512[tid];
        if (tid < 128) delta[tid] = actfn<ACT_SOFTPLUS>(v);
        else           bcv[tid - 128] = v;
    }
    __syncthreads();
}

// ---------------- K2: whole serial chain, 512 threads ----------------
__global__ __launch_bounds__(512, 1)
void k2_chain(const float* __restrict__ conv_b,
              const float* __restrict__ comp_w1, const float* __restrict__ comp_b1,
              const float* __restrict__ comp_w2, const float* __restrict__ comp_b2,
              const float* __restrict__ adapter_w, const float* __restrict__ adapter_b,
              const float* __restrict__ ln_g, const float* __restrict__ ln_b,
              const float* __restrict__ lift_b1, const float* __restrict__ lift_b2,
              const float* __restrict__ net_b1, const float* __restrict__ net_b2,
              const float* __restrict__ fc1_b,
              const float* __restrict__ fc2_b, const float* __restrict__ fc3_b,
              const float* __restrict__ Ag, const float* __restrict__ state_init,
              const float* __restrict__ fcout_b) {
    extern __shared__ __align__(16) unsigned char smraw[];
    float*    biasp   = (float*)(smraw + SB_BIAS);
    float*    red     = (float*)(smraw + SB_RED);
    unsigned* cath2   = (unsigned*)(smraw + SB_CATH2);
    unsigned* l1h2    = (unsigned*)(smraw + SB_L1H2);
    unsigned* neth2   = (unsigned*)(smraw + SB_NETH2);
    unsigned* xth2    = (unsigned*)(smraw + SB_XTH2);
    float*    xtf     = (float*)(smraw + SB_XTF);
    float*    delta_s = (float*)(smraw + SB_DELTA);
    float*    bc      = (float*)(smraw + SB_BC);
    float*    outv    = (float*)(smraw + SB_OUTV);
    unsigned* outvh2  = (unsigned*)(smraw + SB_OUTVH2);
    float*    feat    = (float*)(smraw + SB_FEAT);
    float*    compw   = (float*)(smraw + SB_COMPW);
    float*    dummyf  = (float*)(smraw + SB_DUMMYF);

    const uint4* W_L1 = (const uint4*)(smraw + UB_L1*4);
    const uint4* W_L2 = (const uint4*)(smraw + UB_L2*4);
    const uint4* W_N1 = (const uint4*)(smraw + UB_N1*4);
    const uint4* W_N2 = (const uint4*)(smraw + UB_N2*4);
    const uint4* W_F1 = (const uint4*)(smraw + UB_F1*4);
    const uint4* W_FC23 = (const uint4*)d_pk_fc23;
    const uint4* W_FOUT = (const uint4*)d_pk_fout;

    int tid = threadIdx.x;

    // --- 0. async prefetch of resident pack into smem ---
    {
        const uint4* src = (const uint4*)d_hpack;
        for (int i = tid; i < UPK_TOTAL/4; i += 512)
            cp_async16((uint4*)smraw + i, src + i);
        asm volatile("cp.async.commit_group;");
    }

    // --- 1. reduce GEMM partials -> g in red[n*8+j] ---
    for (int e = tid; e < 968; e += 512) {
        int j = e / 121, n = e % 121;
        float v = conv_b[j];
#pragma unroll 4
        for (int b = 0; b < GP_SLABS; ++b) v += d_gpart[b*968 + e];
        red[n*8 + j] = v;
    }
    __syncthreads();
    if (tid < 256) compw[tid] = comp_w1[tid] + comp_w1[256 + tid];
    else if (tid < 288) compw[tid] = comp_b1[tid - 256];
    else if (tid < 320) compw[tid] = comp_w2[tid - 288];
    for (int e = tid; e < 896; e += 512) {
        int seg = e >> 7, j = e & 127;
        float v = 0.f;
        if (seg == 0) v = lift_b1[j];
        else if (seg == 1) v = (j < 121) ? lift_b2[j] : 0.f;
        else if (seg == 2) v = net_b1[j];
        else if (seg == 3) v = (j < 121) ? net_b2[j] : 0.f;
        else if (seg == 4) v = (j < 121) ? fc1_b[j] : 0.f;
        else if (seg == 5) v = (j < 64) ? fc2_b[j] : fc3_b[j - 64];
        else v = (j < 121) ? fcout_b[j] : 0.f;
        biasp[e] = v;
    }
    if (tid >= 121 && tid < 128) { cath2[tid] = 0u; outvh2[tid] = 0u; }
    __syncthreads();

    // --- 2. feature compressor -> feat[n] ---
    if (tid < 121) {
        float gv[8];
#pragma unroll
        for (int j = 0; j < 8; ++j) gv[j] = red[tid*8 + j];
        float f = comp_b2[0];
#pragma unroll 4
        for (int kk = 0; kk < 32; ++kk) {
            float hh = compw[256 + kk];
#pragma unroll
            for (int i = 0; i < 8; ++i) hh = fmaf(gv[i], compw[i*32 + kk], hh);
            hh = hh > 0.f ? hh : 0.01f * hh;
            f = fmaf(hh, compw[288 + kk], f);
        }
        feat[tid] = f;
    }
    __syncthreads();

    // --- 3. adapter matvec (one-time) ---
    if (tid < 121) {
        float v = adapter_b[tid];
        for (int n = 0; n < 121; ++n) v = fmaf(feat[n], adapter_w[n*121 + tid], v);
        outv[tid] = v;
    }
    __syncthreads();

    // --- 4. layernorm -> q into cath2[0..120] (512-wide tree) ---
    {
        float zv = (tid < 121) ? outv[tid] : 0.f;
        red[tid] = zv;
        red[512 + tid] = zv * zv;
        __syncthreads();
        for (int off = 256; off > 0; off >>= 1) {
            if (tid < off) {
                red[tid] += red[tid + off];
                red[512 + tid] += red[512 + tid + off];
            }
            __syncthreads();
        }
        float mu = red[0] * (1.f / 121.f);
        float var = red[512] * (1.f / 121.f) - mu * mu;
        float rstd = rsqrtf(var + 1e-5f);
        if (tid < 121) {
            float qv = (outv[tid] - mu) * rstd * ln_g[tid] + ln_b[tid];
            __half2 d2 = __half2half2(__float2half_rn(qv));
            cath2[tid] = *(unsigned*)&d2;
        }
    }

    // --- 5. state h + A in registers: 2 groups per thread ---
    float h[2][8], av[2][8];
#pragma unroll
    for (int g = 0; g < 2; ++g) {
        int e = tid + 512*g;
        if (e < 968) {
            int hb = (e >> 3)*64 + (e & 7)*8;
            float4 h0 = *(const float4*)(state_init + hb);
            float4 h1 = *(const float4*)(state_init + hb + 4);
            h[g][0]=h0.x; h[g][1]=h0.y; h[g][2]=h0.z; h[g][3]=h0.w;
            h[g][4]=h1.x; h[g][5]=h1.y; h[g][6]=h1.z; h[g][7]=h1.w;
            float4 a0 = *(const float4*)(Ag + hb);
            float4 a1 = *(const float4*)(Ag + hb + 4);
            av[g][0]=a0.x; av[g][1]=a0.y; av[g][2]=a0.z; av[g][3]=a0.w;
            av[g][4]=a1.x; av[g][5]=a1.y; av[g][6]=a1.z; av[g][7]=a1.w;
        } else {
#pragma unroll
            for (int j = 0; j < 8; ++j) { h[g][j] = 0.f; av[g][j] = 0.f; }
        }
    }
    asm volatile("cp.async.wait_group 0;");
    __syncthreads();

    // --- 6. 7 serial mamba iterations (iter 0 = warmup) ---
#pragma unroll 1
    for (int it = 0; it < 7; ++it) {
        mvh<ACT_RELU, 2>(W_L1, biasp + 0,   cath2, dummyf, l1h2,        red);
        mvh<ACT_TANH, 2>(W_L2, biasp + 128, l1h2,  dummyf, cath2 + 128, red);
        mvh<ACT_RELU, 4>(W_N1, biasp + 256, cath2, dummyf, neth2,       red);
        mvh<ACT_NONE, 2>(W_N2, biasp + 384, neth2, xtf,    xth2,        red);
        mv_fused(W_F1, W_FC23, biasp + 512, xth2, delta_s, bc, red);

        // state update + shuffle out-reduction (no smem round-trip)
#pragma unroll
        for (int g = 0; g < 2; ++g) {
            int e = tid + 512*g;
            int valid = e < 968;
            int sdg = valid ? (e >> 3) : 0;
            int s8g = e & 7;
            float dl = delta_s[sdg];
            float xd = xtf[sdg] * dl;
            float po = 0.f;
#pragma unroll
            for (int j = 0; j < 8; ++j) {
                float z = dl * av[g][j];
                float cel = z > 0.f ? z : (__expf(z) - 1.f);
                float dA = __expf(-cel);
                float hn = fmaf(dA, h[g][j], xd * bc[s8g*8 + j]);
                h[g][j] = hn;
                po = fmaf(bc[64 + s8g*8 + j], hn, po);
            }
            po += __shfl_down_sync(0xffffffffu, po, 4, 8);
            po += __shfl_down_sync(0xffffffffu, po, 2, 8);
            po += __shfl_down_sync(0xffffffffu, po, 1, 8);
            if (valid && s8g == 0) {
                __half2 d2 = __half2half2(__float2half_rn(po));
                outvh2[sdg] = *(unsigned*)&d2;
            }
        }
        __syncthreads();

        if (it > 0) {
            mvh<ACT_NONE, 2>(W_FOUT, biasp + 768, outvh2, dummyf, cath2, red);
            if (tid < 121) d_preds[(it - 1)*121 + tid] = dummyf[tid];
        }
        // it == 0: q (cath2) untouched -> stays z0
    }
}

// ---------------- K3: value-resident broadcast (192 blocks x 1024 thr) ----------------
__global__ __launch_bounds__(1024)
void k3_bcast(float4* __restrict__ out) {
    __shared__ __align__(16) float tile[484];
    int b = blockIdx.x;
    int step = b >> 5;
    int rblk = b & 31;
    int t = threadIdx.x;
    if (t < 484) tile[t] = d_preds[step*121 + (t % 121)];
    __syncthreads();
    if (t < 968) {
        float4 v = ((const float4*)tile)[t % 121];
        long base = (long)step * (STEP_SLAB/4) + (long)rblk * (3*968) + t;
        out[base] = v;
        out[base + 968] = v;
        out[base + 1936] = v;
    }
}

// ---------------- launch ----------------
extern "C" void kernel_launch(void* const* d_in, const int* in_sizes, int n_in,
                              void* d_out, int out_size) {
    const float* x          = (const float*)d_in[0];
    const float* conv_w     = (const float*)d_in[3];
    const float* conv_b     = (const float*)d_in[4];
    const float* comp_w1    = (const float*)d_in[5];
    const float* comp_b1    = (const float*)d_in[6];
    const float* comp_w2    = (const float*)d_in[7];
    const float* comp_b2    = (const float*)d_in[8];
    const float* adapter_w  = (const float*)d_in[9];
    const float* adapter_b  = (const float*)d_in[10];
    const float* ln_g       = (const float*)d_in[11];
    const float* ln_b       = (const float*)d_in[12];
    const float* lift_w1    = (const float*)d_in[13];
    const float* lift_b1    = (const float*)d_in[14];
    const float* lift_w2    = (const float*)d_in[15];
    const float* lift_b2    = (const float*)d_in[16];
    const float* net_w1     = (const float*)d_in[17];
    const float* net_b1     = (const float*)d_in[18];
    const float* net_w2     = (const float*)d_in[19];
    const float* net_b2     = (const float*)d_in[20];
    const float* fc1_w      = (const float*)d_in[21];
    const float* fc1_b      = (const float*)d_in[22];
    const float* fc2_w      = (const float*)d_in[23];
    const float* fc2_b      = (const float*)d_in[24];
    const float* fc3_w      = (const float*)d_in[25];
    const float* fc3_b      = (const float*)d_in[26];
    const float* A          = (const float*)d_in[27];
    const float* state_init = (const float*)d_in[28];
    const float* fcout_w    = (const float*)d_in[29];
    const float* fcout_b    = (const float*)d_in[30];
    (void)in_sizes; (void)n_in;

    cudaFuncSetAttribute(k0, cudaFuncAttributeMaxDynamicSharedMemorySize, K1_SMEM);
    cudaFuncSetAttribute(k2_chain, cudaFuncAttributeMaxDynamicSharedMemorySize, SMEM_BYTES);

    k0<<<K1_BLOCKS + 256, 512, K1_SMEM>>>(x, conv_w, lift_w1, lift_w2, net_w1, net_w2,
                                          fc1_w, fc2_w, fc3_w, fcout_w);

    // serial chain on one block (512 threads, 16 warps)
    k2_chain<<<1, 512, SMEM_BYTES>>>(conv_b, comp_w1, comp_b1, comp_w2, comp_b2,
                                     adapter_w, adapter_b, ln_g, ln_b,
                                     lift_b1, lift_b2, net_b1, net_b2,
                                     fc1_b, fc2_b, fc3_b,
                                     A, state_init, fcout_b);

    k3_bcast<<<192, 1024>>>((float4*)d_out);
}

// round 16
// speedup vs baseline: 1.1628x; 1.1628x over previous
#include <cuda_runtime.h>
#include <cuda_fp16.h>
#include <math.h>

// Problem constants
#define NB 128
#define LL 24
#define NN 121
#define DD 121
#define NSTEP 6
#define BL 3072
#define OUT_TOTAL (NSTEP*BL*NN)
#define STEP_SLAB (BL*NN)

// K1 config: 64 blocks x 48 rows -> 64 gpart slabs (slab k = rows 48k..48k+47)
#define K1_BLOCKS 64
#define K1_ROWS 48
#define GP_SLABS 64
#define K1_SMEM (K1_ROWS*121*4)   // 23232 bytes dynamic

// Resident pack bases in uint units
#define UB_L1 0
#define UB_L2 8192
#define UB_N1 16384
#define UB_N2 32768
#define UB_F1 40960
#define UPK_TOTAL 49152  // uints -> 196608 bytes

// smem byte offsets (k2)
#define SB_BIAS   196608   // float[896]
#define SB_RED    200192   // float[4096]
#define SB_CATH2  216576   // uint[256]
#define SB_L1H2   217600   // uint[128]
#define SB_NETH2  218112   // uint[128]
#define SB_XTH2   218624   // uint[128]
#define SB_XTF    219136   // float[128]
#define SB_DELTA  219648   // float[128]
#define SB_BC     220160   // float[128]
#define SB_OUTV   220672   // float[128]
#define SB_OUTVH2 221184   // uint[128]
#define SB_FEAT   221696   // float[128]
#define SB_COMPW  222208   // float[320]
#define SB_DUMMYF 223488   // float[128]
#define SMEM_BYTES 224000

// ---------------- device scratch ----------------
__device__ float d_gpart[GP_SLABS * 968];   // [slab][out] — coalesced for k2
__device__ float d_preds[NSTEP * DD];
__device__ __align__(16) unsigned int d_hpack[UPK_TOTAL];
__device__ __align__(16) unsigned int d_pk_fc23[8192];
__device__ __align__(16) unsigned int d_pk_fout[8192];

// ---------------- K0: fused k1 partial GEMM + weight packing (512 thr) ----------------
__global__ __launch_bounds__(512)
void k0(const float* __restrict__ x, const float* __restrict__ cw,
        const float* __restrict__ lw1, const float* __restrict__ lw2,
        const float* __restrict__ nw1, const float* __restrict__ nw2,
        const float* __restrict__ f1,  const float* __restrict__ f2,
        const float* __restrict__ f3,  const float* __restrict__ fo) {
    int b = blockIdx.x;
    int t = threadIdx.x;
    if (b < K1_BLOCKS) {
        // ---- k1: stage 48x121 slab (1452 float4) via 512 threads ----
        extern __shared__ __align__(16) float xs[];     // 23232 B
        __shared__ float cwsm[K1_ROWS * 8];
        int r0 = b * K1_ROWS;
        {
            const float4* src = (const float4*)(x + (long)r0 * 121);
            float4* dst = (float4*)xs;
#pragma unroll
            for (int i = 0; i < 3; ++i) {
                int idx = t + i * 512;
                if (idx < 1452) dst[idx] = src[idx];
            }
        }
        if (t < K1_ROWS * 8) cwsm[t] = cw[r0*8 + t];
        __syncthreads();
        if (t < 121) {
            float acc[8];
#pragma unroll
            for (int j = 0; j < 8; ++j) acc[j] = 0.f;
#pragma unroll 4
            for (int r = 0; r < K1_ROWS; ++r) {
                float xv = xs[r*121 + t];
#pragma unroll
                for (int j = 0; j < 8; ++j)
                    acc[j] = fmaf(xv, cwsm[r*8 + j], acc[j]);
            }
#pragma unroll
            for (int j = 0; j < 8; ++j)
                d_gpart[b*968 + j*121 + t] = acc[j];
        }
        return;
    }
    // ---- pack (first 256 threads) ----
    if (t >= 256) return;
    int p = b - K1_BLOCKS;
    int q = t & 31, i = t >> 5;
    int dl = i >> 1;
    int ol = (2*i) & 3;
    int m, sg;
    if      (p < 32)  { m = 0; sg = p; }
    else if (p < 64)  { m = 1; sg = p - 32; }
    else if (p < 128) { m = 2; sg = p - 64; }
    else if (p < 160) { m = 3; sg = p - 128; }
    else if (p < 192) { m = 4; sg = p - 160; }
    else if (p < 224) { m = 5; sg = p - 192; }
    else              { m = 6; sg = p - 224; }
    int k = sg*4 + dl;
    int row, rvalid;
    if (m == 2) {
        row = (k < 128) ? k : (121 + (k - 128));
        rvalid = (k < 128) ? (k < 121) : ((k - 128) < 121);
    } else {
        row = k;
        rvalid = (k < ((m == 1 || m == 3) ? 128 : 121));
    }
    int o0 = q*4 + ol, o1 = o0 + 1;
    float v0 = 0.f, v1 = 0.f;
    if (rvalid) {
        switch (m) {
            case 0: v0 = lw1[row*128 + o0]; v1 = lw1[row*128 + o1]; break;
            case 1: v0 = (o0 < 121) ? lw2[row*121 + o0] : 0.f;
                    v1 = (o1 < 121) ? lw2[row*121 + o1] : 0.f; break;
            case 2: v0 = nw1[row*128 + o0]; v1 = nw1[row*128 + o1]; break;
            case 3: v0 = (o0 < 121) ? nw2[row*121 + o0] : 0.f;
                    v1 = (o1 < 121) ? nw2[row*121 + o1] : 0.f; break;
            case 4: v0 = (o0 < 121) ? f1[row*121 + o0] : 0.f;
                    v1 = (o1 < 121) ? f1[row*121 + o1] : 0.f; break;
            case 5: v0 = (o0 < 64) ? f2[row*64 + o0] : f3[row*64 + o0 - 64];
                    v1 = (o1 < 64) ? f2[row*64 + o1] : f3[row*64 + o1 - 64]; break;
            default:v0 = (o0 < 121) ? fo[row*121 + o0] : 0.f;
                    v1 = (o1 < 121) ? fo[row*121 + o1] : 0.f; break;
        }
    }
    __half2 hh = __floats2half2_rn(v0, v1);
    unsigned u = *(unsigned*)&hh;
    unsigned* dp; unsigned base;
    switch (m) {
        case 0: dp = d_hpack;   base = UB_L1; break;
        case 1: dp = d_hpack;   base = UB_L2; break;
        case 2: dp = d_hpack;   base = UB_N1; break;
        case 3: dp = d_hpack;   base = UB_N2; break;
        case 4: dp = d_hpack;   base = UB_F1; break;
        case 5: dp = d_pk_fc23; base = 0; break;
        default:dp = d_pk_fout; base = 0; break;
    }
    dp[base + (unsigned)sg*256u + (unsigned)(i >> 2)*128u + (unsigned)q*4u + (unsigned)(i & 3)] = u;
}

// ---------------- activations (fast-math) ----------------
#define ACT_NONE 0
#define ACT_RELU 1
#define ACT_TANH 2
#define ACT_SOFTPLUS 3

__device__ __forceinline__ float tanh_fast(float v) {
    float r;
    asm("tanh.approx.f32 %0, %1;" : "=f"(r) : "f"(v));
    return r;
}

template<int ACT>
__device__ __forceinline__ float actfn(float v) {
    if (ACT == ACT_RELU) return v > 0.f ? v : 0.f;
    if (ACT == ACT_TANH) return tanh_fast(v);
    if (ACT == ACT_SOFTPLUS) return v > 20.f ? v : __logf(1.f + __expf(v));
    return v;
}

// ---------------- cp.async ----------------
__device__ __forceinline__ void cp_async16(void* smem_dst, const void* gsrc) {
    unsigned saddr = (unsigned)__cvta_generic_to_shared(smem_dst);
    asm volatile("cp.async.cg.shared.global [%0], [%1], 16;" :: "r"(saddr), "l"(gsrc));
}

// ---------------- half2 chunk ----------------
__device__ __forceinline__ void h2_chunk(uint4 xh, uint4 w0, uint4 w1,
                                         float2& a01, float2& a23) {
    __half2 x0 = *(__half2*)&xh.x, x1 = *(__half2*)&xh.y;
    __half2 x2 = *(__half2*)&xh.z, x3 = *(__half2*)&xh.w;
    __half2 p01 = __hfma2(x0, *(__half2*)&w0.x, __hmul2(x1, *(__half2*)&w0.z));
    __half2 p23 = __hfma2(x0, *(__half2*)&w0.y, __hmul2(x1, *(__half2*)&w0.w));
    float2 f;
    f = __half22float2(p01); a01.x += f.x; a01.y += f.y;
    f = __half22float2(p23); a23.x += f.x; a23.y += f.y;
    p01 = __hfma2(x2, *(__half2*)&w1.x, __hmul2(x3, *(__half2*)&w1.z));
    p23 = __hfma2(x2, *(__half2*)&w1.y, __hmul2(x3, *(__half2*)&w1.w));
    f = __half22float2(p01); a01.x += f.x; a01.y += f.y;
    f = __half22float2(p23); a23.x += f.x; a23.y += f.y;
}

// ---------------- half2 matvec: 128 outputs, 16 slices (1024 thr, s<16 active) ------
template<int ACT, int NSL>
__device__ __forceinline__ void mvh(const uint4* __restrict__ Wt,
                                    const float* __restrict__ biasp,
                                    const unsigned* __restrict__ inh2,
                                    float* __restrict__ outf,
                                    unsigned* __restrict__ outh2,
                                    float* __restrict__ red) {
    int tid = threadIdx.x;
    int q = tid & 31, s = tid >> 5;
    if (s < 16) {
        float2 a01 = make_float2(0.f, 0.f), a23 = make_float2(0.f, 0.f);
#pragma unroll
        for (int cc = 0; cc < NSL; ++cc) {
            int j = s + cc*16;
            uint4 xh = ((const uint4*)inh2)[j];
            const uint4* wb = Wt + j*64;
            h2_chunk(xh, wb[q], wb[q + 32], a01, a23);
        }
        ((float4*)red)[s*32 + q] = make_float4(a01.x, a01.y, a23.x, a23.y);
    }
    __syncthreads();
    if (tid < 128) {
        float v0 = 0.f, v1 = 0.f, v2 = 0.f, v3 = 0.f;
#pragma unroll
        for (int ss = 0; ss < 4; ++ss) {
            v0 += red[(ss*4 + 0)*128 + tid];
            v1 += red[(ss*4 + 1)*128 + tid];
            v2 += red[(ss*4 + 2)*128 + tid];
            v3 += red[(ss*4 + 3)*128 + tid];
        }
        float v = ((v0 + v1) + (v2 + v3)) + biasp[tid];
        v = actfn<ACT>(v);
        outf[tid] = v;
        __half2 d2 = __half2half2(__float2half_rn(v));
        outh2[tid] = *(unsigned*)&d2;
    }
    __syncthreads();
}

// ---------------- fused F1+FC23: 256 outputs, 16 slices x 8 inputs ----------------
__device__ __forceinline__ void mv_fused(const uint4* __restrict__ Wf1,
                                         const uint4* __restrict__ Wfc,
                                         const float* __restrict__ biasp512,
                                         const unsigned* __restrict__ inh2,
                                         float* __restrict__ delta,
                                         float* __restrict__ bcv,
                                         float* __restrict__ red) {
    int tid = threadIdx.x;
    int qq = tid & 63, s = tid >> 6;      // s: 0..15
    int q = qq & 31;
    const uint4* base = (qq < 32) ? Wf1 : Wfc;
    float2 a01 = make_float2(0.f, 0.f), a23 = make_float2(0.f, 0.f);
    uint4 xa = ((const uint4*)inh2)[2*s];
    uint4 xb = ((const uint4*)inh2)[2*s + 1];
    const uint4* wb0 = base + (2*s)*64;
    const uint4* wb1 = base + (2*s + 1)*64;
    h2_chunk(xa, wb0[q], wb0[q + 32], a01, a23);
    h2_chunk(xb, wb1[q], wb1[q + 32], a01, a23);
    ((float4*)red)[s*64 + qq] = make_float4(a01.x, a01.y, a23.x, a23.y);
    __syncthreads();
    if (tid < 256) {
        float v0 = 0.f, v1 = 0.f, v2 = 0.f, v3 = 0.f;
#pragma unroll
        for (int ss = 0; ss < 4; ++ss) {
            v0 += red[(ss*4 + 0)*256 + tid];
            v1 += red[(ss*4 + 1)*256 + tid];
            v2 += red[(ss*4 + 2)*256 + tid];
            v3 += red[(ss*4 + 3)*256 + tid];
        }
        float v = ((v0 + v1) + (v2 + v3)) + biasp512[tid];
        if (tid < 128) delta[tid] = actfn<ACT_SOFTPLUS>(v);
        else           bcv[tid - 128] = v;
    }
    __syncthreads();
}

// ---------------- K2: whole serial chain in one block (1024 thr) ----------------
__global__ __launch_bounds__(1024, 1)
void k2_chain(const float* __restrict__ conv_b,
              const float* __restrict__ comp_w1, const float* __restrict__ comp_b1,
              const float* __restrict__ comp_w2, const float* __restrict__ comp_b2,
              const float* __restrict__ adapter_w, const float* __restrict__ adapter_b,
              const float* __restrict__ ln_g, const float* __restrict__ ln_b,
              const float* __restrict__ lift_b1, const float* __restrict__ lift_b2,
              const float* __restrict__ net_b1, const float* __restrict__ net_b2,
              const float* __restrict__ fc1_b,
              const float* __restrict__ fc2_b, const float* __restrict__ fc3_b,
              const float* __restrict__ Ag, const float* __restrict__ state_init,
              const float* __restrict__ fcout_b) {
    extern __shared__ __align__(16) unsigned char smraw[];
    float*    biasp   = (float*)(smraw + SB_BIAS);
    float*    red     = (float*)(smraw + SB_RED);
    unsigned* cath2   = (unsigned*)(smraw + SB_CATH2);
    unsigned* l1h2    = (unsigned*)(smraw + SB_L1H2);
    unsigned* neth2   = (unsigned*)(smraw + SB_NETH2);
    unsigned* xth2    = (unsigned*)(smraw + SB_XTH2);
    float*    xtf     = (float*)(smraw + SB_XTF);
    float*    delta_s = (float*)(smraw + SB_DELTA);
    float*    bc      = (float*)(smraw + SB_BC);
    float*    outv    = (float*)(smraw + SB_OUTV);
    unsigned* outvh2  = (unsigned*)(smraw + SB_OUTVH2);
    float*    feat    = (float*)(smraw + SB_FEAT);
    float*    compw   = (float*)(smraw + SB_COMPW);
    float*    dummyf  = (float*)(smraw + SB_DUMMYF);

    const uint4* W_L1 = (const uint4*)(smraw + UB_L1*4);
    const uint4* W_L2 = (const uint4*)(smraw + UB_L2*4);
    const uint4* W_N1 = (const uint4*)(smraw + UB_N1*4);
    const uint4* W_N2 = (const uint4*)(smraw + UB_N2*4);
    const uint4* W_F1 = (const uint4*)(smraw + UB_F1*4);
    const uint4* W_FC23 = (const uint4*)d_pk_fc23;
    const uint4* W_FOUT = (const uint4*)d_pk_fout;

    int tid = threadIdx.x;

    // --- 0. async prefetch of resident pack into smem ---
    {
        const uint4* src = (const uint4*)d_hpack;
        for (int i = tid; i < UPK_TOTAL/4; i += 1024)
            cp_async16((uint4*)smraw + i, src + i);
        asm volatile("cp.async.commit_group;");
    }

    // --- 1. reduce GEMM partials (coalesced, 64 slabs) -> g in red[n*8+j] ---
    if (tid < 968) {
        int j = tid / 121, n = tid % 121;
        float v = conv_b[j];
#pragma unroll 4
        for (int b = 0; b < GP_SLABS; ++b) v += d_gpart[b*968 + tid];
        red[n*8 + j] = v;
    }
    __syncthreads();
    if (tid < 256) compw[tid] = comp_w1[tid] + comp_w1[256 + tid];
    else if (tid < 288) compw[tid] = comp_b1[tid - 256];
    else if (tid < 320) compw[tid] = comp_w2[tid - 288];
    if (tid < 896) {
        int seg = tid >> 7, j = tid & 127;
        float v = 0.f;
        if (seg == 0) v = lift_b1[j];
        else if (seg == 1) v = (j < 121) ? lift_b2[j] : 0.f;
        else if (seg == 2) v = net_b1[j];
        else if (seg == 3) v = (j < 121) ? net_b2[j] : 0.f;
        else if (seg == 4) v = (j < 121) ? fc1_b[j] : 0.f;
        else if (seg == 5) v = (j < 64) ? fc2_b[j] : fc3_b[j - 64];
        else v = (j < 121) ? fcout_b[j] : 0.f;
        biasp[tid] = v;
    }
    if (tid >= 121 && tid < 128) { cath2[tid] = 0u; outvh2[tid] = 0u; }
    __syncthreads();

    // --- 2. feature compressor -> feat[n] ---
    if (tid < 121) {
        float gv[8];
#pragma unroll
        for (int j = 0; j < 8; ++j) gv[j] = red[tid*8 + j];
        float f = comp_b2[0];
#pragma unroll 4
        for (int kk = 0; kk < 32; ++kk) {
            float hh = compw[256 + kk];
#pragma unroll
            for (int i = 0; i < 8; ++i) hh = fmaf(gv[i], compw[i*32 + kk], hh);
            hh = hh > 0.f ? hh : 0.01f * hh;
            f = fmaf(hh, compw[288 + kk], f);
        }
        feat[tid] = f;
    }
    __syncthreads();

    // --- 3. adapter matvec (one-time) ---
    if (tid < 121) {
        float v = adapter_b[tid];
        for (int n = 0; n < 121; ++n) v = fmaf(feat[n], adapter_w[n*121 + tid], v);
        outv[tid] = v;
    }
    __syncthreads();

    // --- 4. layernorm -> q into cath2[0..120] (dup-half2) ---
    {
        float zv = (tid < 121) ? outv[tid] : 0.f;
        red[tid] = zv;
        red[1024 + tid] = zv * zv;
        __syncthreads();
        for (int off = 512; off > 0; off >>= 1) {
            if (tid < off) {
                red[tid] += red[tid + off];
                red[1024 + tid] += red[1024 + tid + off];
            }
            __syncthreads();
        }
        float mu = red[0] * (1.f / 121.f);
        float var = red[1024] * (1.f / 121.f) - mu * mu;
        float rstd = rsqrtf(var + 1e-5f);
        if (tid < 121) {
            float qv = (outv[tid] - mu) * rstd * ln_g[tid] + ln_b[tid];
            __half2 d2 = __half2half2(__float2half_rn(qv));
            cath2[tid] = *(unsigned*)&d2;
        }
    }

    // --- 5. state h + A in registers ---
    float h[8], av[8];
    int sd = tid >> 3, s8 = tid & 7;
    int hbase = sd * 64 + s8 * 8;
    if (tid < 968) {
        float4 h0 = *(const float4*)(state_init + hbase);
        float4 h1 = *(const float4*)(state_init + hbase + 4);
        h[0]=h0.x; h[1]=h0.y; h[2]=h0.z; h[3]=h0.w;
        h[4]=h1.x; h[5]=h1.y; h[6]=h1.z; h[7]=h1.w;
        float4 a0 = *(const float4*)(Ag + hbase);
        float4 a1 = *(const float4*)(Ag + hbase + 4);
        av[0]=a0.x; av[1]=a0.y; av[2]=a0.z; av[3]=a0.w;
        av[4]=a1.x; av[5]=a1.y; av[6]=a1.z; av[7]=a1.w;
    }
    asm volatile("cp.async.wait_group 0;");
    __syncthreads();

    // --- 6. 7 serial mamba iterations (iter 0 = warmup) ---
#pragma unroll 1
    for (int it = 0; it < 7; ++it) {
        mvh<ACT_RELU, 2>(W_L1, biasp + 0,   cath2, dummyf, l1h2,        red);
        mvh<ACT_TANH, 2>(W_L2, biasp + 128, l1h2,  dummyf, cath2 + 128, red);
        mvh<ACT_RELU, 4>(W_N1, biasp + 256, cath2, dummyf, neth2,       red);
        mvh<ACT_NONE, 2>(W_N2, biasp + 384, neth2, xtf,    xth2,        red);
        mv_fused(W_F1, W_FC23, biasp + 512, xth2, delta_s, bc, red);

        // state update + partial out (fast exp)
        if (tid < 968) {
            float dl = delta_s[sd];
            float xd = xtf[sd] * dl;
            float po = 0.f;
#pragma unroll
            for (int j = 0; j < 8; ++j) {
                float z = dl * av[j];
                float cel = z > 0.f ? z : (__expf(z) - 1.f);
                float dA = __expf(-cel);
                float hn = fmaf(dA, h[j], xd * bc[s8*8 + j]);
                h[j] = hn;
                po = fmaf(bc[64 + s8*8 + j], hn, po);
            }
            red[tid] = po;
        }
        __syncthreads();
        if (tid < 121) {
            float v0 = red[tid*8+0] + red[tid*8+1];
            float v1 = red[tid*8+2] + red[tid*8+3];
            float v2 = red[tid*8+4] + red[tid*8+5];
            float v3 = red[tid*8+6] + red[tid*8+7];
            float v = (v0 + v1) + (v2 + v3);
            outv[tid] = v;
            __half2 d2 = __half2half2(__float2half_rn(v));
            outvh2[tid] = *(unsigned*)&d2;
        }
        __syncthreads();

        if (it > 0) {
            mvh<ACT_NONE, 2>(W_FOUT, biasp + 768, outvh2, dummyf, cath2, red);
            if (tid < 121) d_preds[(it - 1)*121 + tid] = dummyf[tid];
        }
        // it == 0: q (cath2) untouched -> stays z0
    }
}

// ---------------- K3: value-resident broadcast (192 blocks x 1024 thr) ----------------
__global__ __launch_bounds__(1024)
void k3_bcast(float4* __restrict__ out) {
    __shared__ __align__(16) float tile[484];
    int b = blockIdx.x;
    int step = b >> 5;
    int rblk = b & 31;
    int t = threadIdx.x;
    if (t < 484) tile[t] = d_preds[step*121 + (t % 121)];
    __syncthreads();
    if (t < 968) {
        float4 v = ((const float4*)tile)[t % 121];
        long base = (long)step * (STEP_SLAB/4) + (long)rblk * (3*968) + t;
        out[base] = v;
        out[base + 968] = v;
        out[base + 1936] = v;
    }
}

// ---------------- launch ----------------
extern "C" void kernel_launch(void* const* d_in, const int* in_sizes, int n_in,
                              void* d_out, int out_size) {
    const float* x          = (const float*)d_in[0];
    const float* conv_w     = (const float*)d_in[3];
    const float* conv_b     = (const float*)d_in[4];
    const float* comp_w1    = (const float*)d_in[5];
    const float* comp_b1    = (const float*)d_in[6];
    const float* comp_w2    = (const float*)d_in[7];
    const float* comp_b2    = (const float*)d_in[8];
    const float* adapter_w  = (const float*)d_in[9];
    const float* adapter_b  = (const float*)d_in[10];
    const float* ln_g       = (const float*)d_in[11];
    const float* ln_b       = (const float*)d_in[12];
    const float* lift_w1    = (const float*)d_in[13];
    const float* lift_b1    = (const float*)d_in[14];
    const float* lift_w2    = (const float*)d_in[15];
    const float* lift_b2    = (const float*)d_in[16];
    const float* net_w1     = (const float*)d_in[17];
    const float* net_b1     = (const float*)d_in[18];
    const float* net_w2     = (const float*)d_in[19];
    const float* net_b2     = (const float*)d_in[20];
    const float* fc1_w      = (const float*)d_in[21];
    const float* fc1_b      = (const float*)d_in[22];
    const float* fc2_w      = (const float*)d_in[23];
    const float* fc2_b      = (const float*)d_in[24];
    const float* fc3_w      = (const float*)d_in[25];
    const float* fc3_b      = (const float*)d_in[26];
    const float* A          = (const float*)d_in[27];
    const float* state_init = (const float*)d_in[28];
    const float* fcout_w    = (const float*)d_in[29];
    const float* fcout_b    = (const float*)d_in[30];
    (void)in_sizes; (void)n_in;

    cudaFuncSetAttribute(k0, cudaFuncAttributeMaxDynamicSharedMemorySize, K1_SMEM);
    cudaFuncSetAttribute(k2_chain, cudaFuncAttributeMaxDynamicSharedMemorySize, SMEM_BYTES);

    // fused k1 (64 blocks x 48 rows) + pack (256 blocks)
    k0<<<K1_BLOCKS + 256, 512, K1_SMEM>>>(x, conv_w, lift_w1, lift_w2, net_w1, net_w2,
                                          fc1_w, fc2_w, fc3_w, fcout_w);

    // serial chain on one block (1024 threads — proven best config)
    k2_chain<<<1, 1024, SMEM_BYTES>>>(conv_b, comp_w1, comp_b1, comp_w2, comp_b2,
                                      adapter_w, adapter_b, ln_g, ln_b,
                                      lift_b1, lift_b2, net_b1, net_b2,
                                      fc1_b, fc2_b, fc3_b,
                                      A, state_init, fcout_b);

    k3_bcast<<<192, 1024>>>((float4*)d_out);
}